// round 9
// baseline (speedup 1.0000x reference)
#include <cuda_runtime.h>
#include <cuda_bf16.h>
#include <stdint.h>
#include <math.h>

#define B_ 4
#define S_ 1500
#define SP_ 1504
#define E_ 1280
#define H_ 20
#define D_ 64
#define M_ 6000
#define GS2 40          // gemm smem row stride (elems): conflict-free ldsm/sts
#define AS 72           // attn smem row stride

// Persistent split-bf16 operands (device globals: allocation-free rule)
__device__ __align__(128) __nv_bfloat16 g_xh[(size_t)M_*E_];
__device__ __align__(128) __nv_bfloat16 g_xl[(size_t)M_*E_];
__device__ __align__(128) __nv_bfloat16 g_wh[(size_t)4*E_*E_];
__device__ __align__(128) __nv_bfloat16 g_wl[(size_t)4*E_*E_];
__device__ __align__(128) __nv_bfloat16 g_qh[(size_t)B_*H_*S_*D_];
__device__ __align__(128) __nv_bfloat16 g_ql[(size_t)B_*H_*S_*D_];
__device__ __align__(128) __nv_bfloat16 g_kh[(size_t)B_*H_*S_*D_];
__device__ __align__(128) __nv_bfloat16 g_kl[(size_t)B_*H_*S_*D_];
__device__ __align__(128) __nv_bfloat16 g_vth[(size_t)B_*H_*D_*SP_];
__device__ __align__(128) __nv_bfloat16 g_vtl[(size_t)B_*H_*D_*SP_];
__device__ __align__(128) __nv_bfloat16 g_ch[(size_t)M_*E_];
__device__ __align__(128) __nv_bfloat16 g_cl[(size_t)M_*E_];

__device__ __forceinline__ uint32_t sptr(const void* p) {
    return (uint32_t)__cvta_generic_to_shared(p);
}
__device__ __forceinline__ void ldsm4(uint32_t* r, uint32_t a) {
    asm volatile("ldmatrix.sync.aligned.m8n8.x4.shared.b16 {%0,%1,%2,%3},[%4];"
                 : "=r"(r[0]), "=r"(r[1]), "=r"(r[2]), "=r"(r[3]) : "r"(a));
}
__device__ __forceinline__ void mma16816(float* c, const uint32_t* a,
                                         uint32_t b0, uint32_t b1) {
    asm volatile(
        "mma.sync.aligned.m16n8k16.row.col.f32.bf16.bf16.f32 "
        "{%0,%1,%2,%3},{%4,%5,%6,%7},{%8,%9},{%0,%1,%2,%3};"
        : "+f"(c[0]), "+f"(c[1]), "+f"(c[2]), "+f"(c[3])
        : "r"(a[0]), "r"(a[1]), "r"(a[2]), "r"(a[3]), "r"(b0), "r"(b1));
}
__device__ __forceinline__ void split_pack(float x, float y, uint32_t& hi, uint32_t& lo) {
    __nv_bfloat16 hx = __float2bfloat16_rn(x), hy = __float2bfloat16_rn(y);
    __nv_bfloat16 lx = __float2bfloat16_rn(x - __bfloat162float(hx));
    __nv_bfloat16 ly = __float2bfloat16_rn(y - __bfloat162float(hy));
    __nv_bfloat162 hh; hh.x = hx; hh.y = hy;
    __nv_bfloat162 ll; ll.x = lx; ll.y = ly;
    hi = *reinterpret_cast<uint32_t*>(&hh);
    lo = *reinterpret_cast<uint32_t*>(&ll);
}
__device__ __forceinline__ void cpa16(uint32_t dst, const void* src) {
    asm volatile("cp.async.ca.shared.global [%0], [%1], 16;" :: "r"(dst), "l"(src));
}

// ---------------------------------------------------------------------------
// Prologue: split fp32 -> bf16 hi/lo.  sel 0: -> g_xh/g_xl; sel 1: -> g_w*+off
// ---------------------------------------------------------------------------
__global__ __launch_bounds__(256) void splitk(const float4* __restrict__ src,
                                              int sel, size_t off, int n4)
{
    int i = blockIdx.x * 256 + threadIdx.x;
    if (i >= n4) return;
    __nv_bfloat16 *h, *l;
    if (sel == 0) { h = g_xh; l = g_xl; } else { h = g_wh + off; l = g_wl + off; }
    float4 v = src[i];
    uint32_t h01, l01, h23, l23;
    split_pack(v.x, v.y, h01, l01);
    split_pack(v.z, v.w, h23, l23);
    *(uint2*)&h[(size_t)i*4] = make_uint2(h01, h23);
    *(uint2*)&l[(size_t)i*4] = make_uint2(l01, l23);
}

// ---------------------------------------------------------------------------
// Split-bf16 tensor GEMM, cp.async double-buffered, 128x128x32 tiles.
// A = x (modes 1..3) or ctx (mode 0), already split.  W selected by mode.
// mode 0: fp32 [M,E] + bias.  1: ->q hi/lo (+b)*0.125.  2: ->k.  3: ->v^T (+b).
// ---------------------------------------------------------------------------
__global__ __launch_bounds__(256) void gemm_v2(const float* __restrict__ bias,
                                               float* __restrict__ out, int mode)
{
    extern __shared__ __nv_bfloat16 dsm[];
    const int ARR = 128 * GS2;          // elems per array
    const int STG = 4 * ARR;            // elems per stage (Ah,Al,Bh,Bl)

    int tid = threadIdx.x, lane = tid & 31, warp = tid >> 5;
    int m0 = blockIdx.x * 128, n0 = blockIdx.y * 128;
    int wm = (warp >> 1) * 32, wn = (warp & 1) * 64;

    const __nv_bfloat16 *Ah, *Al;
    if (mode == 0) { Ah = g_ch; Al = g_cl; } else { Ah = g_xh; Al = g_xl; }
    size_t woff = (size_t)((mode == 0) ? 3 : (mode - 1)) * E_ * E_;
    const __nv_bfloat16 *Bh = g_wh + woff, *Bl = g_wl + woff;

    // zero invalid A rows (last m-block only), both stages & hl
    int nInv = m0 + 128 - M_;
    if (nInv > 0) {
        for (int i = tid; i < nInv * GS2; i += 256) {
            int r = 128 - nInv + i / GS2, c = i % GS2;
#pragma unroll
            for (int s = 0; s < 2; s++)
#pragma unroll
                for (int a = 0; a < 2; a++)
                    dsm[s*STG + a*ARR + r*GS2 + c] = __float2bfloat16_rn(0.f);
        }
    }

    float acc[2][8][4];
#pragma unroll
    for (int a = 0; a < 2; a++)
#pragma unroll
        for (int nb = 0; nb < 8; nb++)
#pragma unroll
            for (int r = 0; r < 4; r++) acc[a][nb][r] = 0.f;

    // loader mapping: row = tid&127, col half = (tid>>7)*16 (2x16B per array)
    int lr = tid & 127, lc = (tid >> 7) * 16;
    bool aok = (m0 + lr) < M_;
    const __nv_bfloat16* aph = Ah + (size_t)(m0 + lr) * E_ + lc;
    const __nv_bfloat16* apl = Al + (size_t)(m0 + lr) * E_ + lc;
    const __nv_bfloat16* bph = Bh + (size_t)(n0 + lr) * E_ + lc;
    const __nv_bfloat16* bpl = Bl + (size_t)(n0 + lr) * E_ + lc;
    uint32_t sb = sptr(dsm);
    uint32_t dAh = sb + (0*ARR + lr*GS2 + lc) * 2;
    uint32_t dAl = sb + (1*ARR + lr*GS2 + lc) * 2;
    uint32_t dBh = sb + (2*ARR + lr*GS2 + lc) * 2;
    uint32_t dBl = sb + (3*ARR + lr*GS2 + lc) * 2;
    const uint32_t SB = STG * 2;   // stage stride bytes

    const int NK = E_ / 32;        // 40

#define ISSUE(s, kc) do {                                                   \
        uint32_t so = (uint32_t)(s) * SB;                                   \
        size_t go = (size_t)(kc) * 32;                                      \
        if (aok) {                                                          \
            cpa16(dAh + so,      aph + go);                                 \
            cpa16(dAh + so + 16, aph + go + 8);                             \
            cpa16(dAl + so,      apl + go);                                 \
            cpa16(dAl + so + 16, apl + go + 8);                             \
        }                                                                   \
        cpa16(dBh + so,      bph + go);                                     \
        cpa16(dBh + so + 16, bph + go + 8);                                 \
        cpa16(dBl + so,      bpl + go);                                     \
        cpa16(dBl + so + 16, bpl + go + 8);                                 \
        asm volatile("cp.async.commit_group;");                             \
    } while (0)

    ISSUE(0, 0);

    int arow = wm + (lane & 7) + ((lane >> 3) & 1) * 8;
    int brow = wn + (lane & 7) + (lane >> 4) * 8;

    for (int kc = 0; kc < NK; kc++) {
        if (kc + 1 < NK) {
            ISSUE((kc + 1) & 1, kc + 1);
            asm volatile("cp.async.wait_group 1;");
        } else {
            asm volatile("cp.async.wait_group 0;");
        }
        __syncthreads();

        const __nv_bfloat16* st = dsm + (kc & 1) * STG;
#pragma unroll
        for (int cc = 0; cc < 2; cc++) {
            int akof = cc * 16 + (lane >> 4) * 8;
            int bkof = cc * 16 + ((lane >> 3) & 1) * 8;
            uint32_t ah[2][4], al[2][4];
#pragma unroll
            for (int a = 0; a < 2; a++) {
                ldsm4(ah[a], sptr(&st[0*ARR + (arow + a*16)*GS2 + akof]));
                ldsm4(al[a], sptr(&st[1*ARR + (arow + a*16)*GS2 + akof]));
            }
            uint32_t bh[4][4], bl[4][4];
#pragma unroll
            for (int p = 0; p < 4; p++) {
                ldsm4(bh[p], sptr(&st[2*ARR + (brow + p*16)*GS2 + bkof]));
                ldsm4(bl[p], sptr(&st[3*ARR + (brow + p*16)*GS2 + bkof]));
            }
            // pass-major: no back-to-back same-acc mma
#pragma unroll
            for (int pass = 0; pass < 3; pass++) {
#pragma unroll
                for (int a = 0; a < 2; a++) {
                    const uint32_t* af = (pass < 2) ? ah[a] : al[a];
#pragma unroll
                    for (int nb = 0; nb < 8; nb++) {
                        const uint32_t (*bf)[4] = (pass == 1) ? bl : bh;
                        mma16816(acc[a][nb], af,
                                 bf[nb>>1][(nb&1)*2], bf[nb>>1][(nb&1)*2+1]);
                    }
                }
            }
        }
        __syncthreads();
    }
#undef ISSUE

    // epilogue
#pragma unroll
    for (int a = 0; a < 2; a++)
#pragma unroll
        for (int rr = 0; rr < 2; rr++) {
            int gm = m0 + wm + a*16 + (lane >> 2) + rr*8;
            if (gm >= M_) continue;
            int bb = gm / S_, ss = gm % S_;
#pragma unroll
            for (int nb = 0; nb < 8; nb++) {
                int n = n0 + wn + nb*8 + (lane & 3)*2;
                float v0 = acc[a][nb][rr*2+0], v1 = acc[a][nb][rr*2+1];
                if (mode == 0) {
                    float2 o; o.x = v0 + bias[n]; o.y = v1 + bias[n+1];
                    *(float2*)&out[(size_t)gm*E_ + n] = o;
                } else {
                    if (mode == 1) { v0 = (v0+bias[n])*0.125f; v1 = (v1+bias[n+1])*0.125f; }
                    else if (mode == 3) { v0 += bias[n]; v1 += bias[n+1]; }
                    int hh = n >> 6, dd = n & 63;
                    uint32_t hi, lo;
                    split_pack(v0, v1, hi, lo);
                    if (mode == 3) {
                        size_t base = (((size_t)bb*H_ + hh)*D_ + dd)*SP_ + ss;
                        __nv_bfloat162 Hh = *(__nv_bfloat162*)&hi;
                        __nv_bfloat162 Ll = *(__nv_bfloat162*)&lo;
                        g_vth[base] = Hh.x; g_vth[base+SP_] = Hh.y;
                        g_vtl[base] = Ll.x; g_vtl[base+SP_] = Ll.y;
                    } else {
                        size_t idx = (((size_t)bb*H_ + hh)*S_ + ss)*D_ + dd;
                        if (mode == 1) { *(uint32_t*)&g_qh[idx] = hi; *(uint32_t*)&g_ql[idx] = lo; }
                        else           { *(uint32_t*)&g_kh[idx] = hi; *(uint32_t*)&g_kl[idx] = lo; }
                    }
                }
            }
        }
}

// ---------------------------------------------------------------------------
// Tensor-core flash attention: 256 thr (8 warps x 16 q = 128 q rows/block).
// 64-key chunks; online softmax on fragments; in-register P repack for P@V;
// pass-major mma ordering; ctx written as split bf16.
// ---------------------------------------------------------------------------
__global__ __launch_bounds__(256) void attn_tc(const float* __restrict__ mask)
{
    __shared__ __align__(16) __nv_bfloat16 SM[4*64*AS];
    __nv_bfloat16* sK = SM;                 // [hl][64][AS]
    __nv_bfloat16* sV = SM + 2*64*AS;

    int tid = threadIdx.x, lane = tid & 31, warp = tid >> 5;
    int qb = blockIdx.x, bh = blockIdx.y;
    int b = bh / H_;
    const __nv_bfloat16* qhp = g_qh  + (size_t)bh*S_*D_;
    const __nv_bfloat16* qlp = g_ql  + (size_t)bh*S_*D_;
    const __nv_bfloat16* khp = g_kh  + (size_t)bh*S_*D_;
    const __nv_bfloat16* klp = g_kl  + (size_t)bh*S_*D_;
    const __nv_bfloat16* vhp = g_vth + (size_t)bh*D_*SP_;
    const __nv_bfloat16* vlp = g_vtl + (size_t)bh*D_*SP_;
    int s0q = qb * 128;

    // stage 128 q rows (hi/lo) across full smem, build persistent A fragments
#pragma unroll
    for (int it = 0; it < 8; it++) {
        int idx = it*256 + tid;
        int hl = idx >> 10, r = (idx >> 3) & 127, c8 = idx & 7;
        const __nv_bfloat16* src = hl ? qlp : qhp;
        uint4 v = make_uint4(0u,0u,0u,0u);
        if (s0q + r < S_) v = *(const uint4*)(src + (size_t)(s0q+r)*D_ + c8*8);
        *(uint4*)&SM[hl*128*AS + r*AS + c8*8] = v;
    }
    __syncthreads();

    uint32_t qf[2][4][4];
    {
        int arow = warp*16 + (lane & 7) + ((lane >> 3) & 1)*8;
        int akof = (lane >> 4)*8;
#pragma unroll
        for (int hl = 0; hl < 2; hl++)
#pragma unroll
            for (int kb = 0; kb < 4; kb++)
                ldsm4(qf[hl][kb], sptr(&SM[hl*128*AS + arow*AS + kb*16 + akof]));
    }
    __syncthreads();

    float oacc[8][4];
#pragma unroll
    for (int d = 0; d < 8; d++)
#pragma unroll
        for (int r = 0; r < 4; r++) oacc[d][r] = 0.f;
    float mi0 = -1e30f, mi1 = -1e30f, li0 = 0.f, li1 = 0.f;

    int r0 = warp*16 + (lane >> 2);
    int sq0 = s0q + r0, sq1 = sq0 + 8;
    const float* mrow0 = mask + ((size_t)b*S_ + (sq0 < S_ ? sq0 : S_-1))*S_;
    const float* mrow1 = mask + ((size_t)b*S_ + (sq1 < S_ ? sq1 : S_-1))*S_;

    int brow = (lane & 7) + (lane >> 4)*8;
    int bkof = ((lane >> 3) & 1)*8;

    const int NC = (S_ + 63) / 64;   // 24
    for (int kc = 0; kc < NC; kc++) {
        int s0 = kc * 64;
        if (s0 + 64 <= S_) {
#pragma unroll
            for (int it = 0; it < 4; it++) {
                int idx = it*256 + tid;
                int hl = idx >> 9, r = (idx >> 3) & 63, c8 = idx & 7;
                const __nv_bfloat16* ks = hl ? klp : khp;
                const __nv_bfloat16* vs = hl ? vlp : vhp;
                *(uint4*)&sK[hl*64*AS + r*AS + c8*8] =
                    *(const uint4*)(ks + (size_t)(s0+r)*D_ + c8*8);
                *(uint4*)&sV[hl*64*AS + r*AS + c8*8] =
                    *(const uint4*)(vs + (size_t)r*SP_ + s0 + c8*8);
            }
        } else {
#pragma unroll
            for (int it = 0; it < 4; it++) {
                int idx = it*256 + tid;
                int hl = idx >> 9, r = (idx >> 3) & 63, c8 = idx & 7;
                const __nv_bfloat16* ks = hl ? klp : khp;
                const __nv_bfloat16* vs = hl ? vlp : vhp;
                uint4 kv = make_uint4(0u,0u,0u,0u);
                if (s0 + r < S_) kv = *(const uint4*)(ks + (size_t)(s0+r)*D_ + c8*8);
                *(uint4*)&sK[hl*64*AS + r*AS + c8*8] = kv;
                uint4 vv; __nv_bfloat16* tp = (__nv_bfloat16*)&vv;
#pragma unroll
                for (int e = 0; e < 8; e++) {
                    int s = s0 + c8*8 + e;
                    tp[e] = (s < S_) ? vs[(size_t)r*SP_ + s] : __float2bfloat16_rn(0.f);
                }
                *(uint4*)&sV[hl*64*AS + r*AS + c8*8] = vv;
            }
        }
        __syncthreads();

        // S = Q @ K^T (3-pass split, pass-major)
        float sc[8][4];
#pragma unroll
        for (int nb = 0; nb < 8; nb++)
#pragma unroll
            for (int r = 0; r < 4; r++) sc[nb][r] = 0.f;
#pragma unroll
        for (int kb = 0; kb < 4; kb++) {
            uint32_t khf[4][4], klf[4][4];
#pragma unroll
            for (int p = 0; p < 4; p++) {
                ldsm4(khf[p], sptr(&sK[0*64*AS + (brow+p*16)*AS + kb*16 + bkof]));
                ldsm4(klf[p], sptr(&sK[1*64*AS + (brow+p*16)*AS + kb*16 + bkof]));
            }
#pragma unroll
            for (int pass = 0; pass < 3; pass++) {
                const uint32_t* af = (pass < 2) ? qf[0][kb] : qf[1][kb];
#pragma unroll
                for (int nb = 0; nb < 8; nb++) {
                    const uint32_t (*bf)[4] = (pass == 1) ? klf : khf;
                    mma16816(sc[nb], af, bf[nb>>1][(nb&1)*2], bf[nb>>1][(nb&1)*2+1]);
                }
            }
        }

        // mask + online softmax
        float mnew0 = mi0, mnew1 = mi1;
        int colb = s0 + (lane & 3)*2;
#pragma unroll
        for (int nb = 0; nb < 8; nb++) {
            int col = colb + nb*8;
            float2 mk0 = make_float2(-1e30f, -1e30f), mk1 = mk0;
            if (col < S_) { mk0 = *(const float2*)(mrow0 + col);
                            mk1 = *(const float2*)(mrow1 + col); }
            sc[nb][0] += mk0.x; sc[nb][1] += mk0.y;
            sc[nb][2] += mk1.x; sc[nb][3] += mk1.y;
            mnew0 = fmaxf(mnew0, fmaxf(sc[nb][0], sc[nb][1]));
            mnew1 = fmaxf(mnew1, fmaxf(sc[nb][2], sc[nb][3]));
        }
        mnew0 = fmaxf(mnew0, __shfl_xor_sync(0xffffffffu, mnew0, 1));
        mnew0 = fmaxf(mnew0, __shfl_xor_sync(0xffffffffu, mnew0, 2));
        mnew1 = fmaxf(mnew1, __shfl_xor_sync(0xffffffffu, mnew1, 1));
        mnew1 = fmaxf(mnew1, __shfl_xor_sync(0xffffffffu, mnew1, 2));
        float corr0 = __expf(mi0 - mnew0), corr1 = __expf(mi1 - mnew1);
        float rs0 = 0.f, rs1 = 0.f;
#pragma unroll
        for (int nb = 0; nb < 8; nb++) {
            sc[nb][0] = __expf(sc[nb][0] - mnew0);
            sc[nb][1] = __expf(sc[nb][1] - mnew0);
            sc[nb][2] = __expf(sc[nb][2] - mnew1);
            sc[nb][3] = __expf(sc[nb][3] - mnew1);
            rs0 += sc[nb][0] + sc[nb][1];
            rs1 += sc[nb][2] + sc[nb][3];
        }
        rs0 += __shfl_xor_sync(0xffffffffu, rs0, 1);
        rs0 += __shfl_xor_sync(0xffffffffu, rs0, 2);
        rs1 += __shfl_xor_sync(0xffffffffu, rs1, 1);
        rs1 += __shfl_xor_sync(0xffffffffu, rs1, 2);
        li0 = li0*corr0 + rs0; li1 = li1*corr1 + rs1;
        mi0 = mnew0; mi1 = mnew1;
#pragma unroll
        for (int d = 0; d < 8; d++) {
            oacc[d][0] *= corr0; oacc[d][1] *= corr0;
            oacc[d][2] *= corr1; oacc[d][3] *= corr1;
        }

        // O += P @ V (in-register P repack, 3-pass split, pass-major)
#pragma unroll
        for (int kb = 0; kb < 4; kb++) {
            uint32_t ph[4], pl[4];
            split_pack(sc[2*kb][0],   sc[2*kb][1],   ph[0], pl[0]);
            split_pack(sc[2*kb][2],   sc[2*kb][3],   ph[1], pl[1]);
            split_pack(sc[2*kb+1][0], sc[2*kb+1][1], ph[2], pl[2]);
            split_pack(sc[2*kb+1][2], sc[2*kb+1][3], ph[3], pl[3]);
            uint32_t vhf[4][4], vlf[4][4];
#pragma unroll
            for (int p = 0; p < 4; p++) {
                ldsm4(vhf[p], sptr(&sV[0*64*AS + (brow+p*16)*AS + kb*16 + bkof]));
                ldsm4(vlf[p], sptr(&sV[1*64*AS + (brow+p*16)*AS + kb*16 + bkof]));
            }
#pragma unroll
            for (int pass = 0; pass < 3; pass++) {
                const uint32_t* af = (pass < 2) ? ph : pl;
#pragma unroll
                for (int db = 0; db < 8; db++) {
                    const uint32_t (*bf)[4] = (pass == 1) ? vlf : vhf;
                    mma16816(oacc[db], af, bf[db>>1][(db&1)*2], bf[db>>1][(db&1)*2+1]);
                }
            }
        }
        __syncthreads();
    }

    float inv0 = 1.f/li0, inv1 = 1.f/li1;
    int hcol = (bh % H_) * 64;
#pragma unroll
    for (int db = 0; db < 8; db++) {
        int col = hcol + db*8 + (lane & 3)*2;
        if (sq0 < S_) {
            uint32_t hi, lo;
            split_pack(oacc[db][0]*inv0, oacc[db][1]*inv0, hi, lo);
            size_t idx = ((size_t)b*S_ + sq0)*E_ + col;
            *(uint32_t*)&g_ch[idx] = hi; *(uint32_t*)&g_cl[idx] = lo;
        }
        if (sq1 < S_) {
            uint32_t hi, lo;
            split_pack(oacc[db][2]*inv1, oacc[db][3]*inv1, hi, lo);
            size_t idx = ((size_t)b*S_ + sq1)*E_ + col;
            *(uint32_t*)&g_ch[idx] = hi; *(uint32_t*)&g_cl[idx] = lo;
        }
    }
}

// ---------------------------------------------------------------------------
extern "C" void kernel_launch(void* const* d_in, const int* in_sizes, int n_in,
                              void* d_out, int out_size)
{
    const float* x    = (const float*)d_in[0];
    const float* mask = (const float*)d_in[1];
    const float* Wq   = (const float*)d_in[2];
    const float* bq   = (const float*)d_in[3];
    const float* Wk   = (const float*)d_in[4];
    const float* Wv   = (const float*)d_in[5];
    const float* bv   = (const float*)d_in[6];
    const float* Wo   = (const float*)d_in[7];
    const float* bo   = (const float*)d_in[8];
    float* out = (float*)d_out;

    const int GSMEM = 2 * 4 * 128 * GS2 * (int)sizeof(__nv_bfloat16);  // 81920 B
    cudaFuncSetAttribute(gemm_v2, cudaFuncAttributeMaxDynamicSharedMemorySize, GSMEM);

    // prologue: split fp32 operands into persistent bf16 hi/lo
    int n4x = M_ * E_ / 4;
    int n4w = E_ * E_ / 4;
    splitk<<<(n4x + 255) / 256, 256>>>((const float4*)x,  0, 0, n4x);
    splitk<<<(n4w + 255) / 256, 256>>>((const float4*)Wq, 1, (size_t)0*E_*E_, n4w);
    splitk<<<(n4w + 255) / 256, 256>>>((const float4*)Wk, 1, (size_t)1*E_*E_, n4w);
    splitk<<<(n4w + 255) / 256, 256>>>((const float4*)Wv, 1, (size_t)2*E_*E_, n4w);
    splitk<<<(n4w + 255) / 256, 256>>>((const float4*)Wo, 1, (size_t)3*E_*E_, n4w);

    dim3 ggrid((M_ + 127) / 128, E_ / 128);          // (47, 10)
    gemm_v2<<<ggrid, 256, GSMEM>>>(bq, nullptr, 1);
    gemm_v2<<<ggrid, 256, GSMEM>>>(nullptr, nullptr, 2);
    gemm_v2<<<ggrid, 256, GSMEM>>>(bv, nullptr, 3);

    dim3 agrid((S_ + 127) / 128, B_ * H_);           // (12, 80)
    attn_tc<<<agrid, 256>>>(mask);

    gemm_v2<<<ggrid, 256, GSMEM>>>(bo, out, 0);
}

// round 10
// speedup vs baseline: 1.1427x; 1.1427x over previous
#include <cuda_runtime.h>
#include <cuda_bf16.h>
#include <stdint.h>
#include <math.h>

#define B_ 4
#define S_ 1500
#define SP_ 1504
#define E_ 1280
#define H_ 20
#define D_ 64
#define M_ 6000
#define GS 24           // gemm smem row stride (elems)
#define AS 72           // attn smem row stride

// Persistent split-bf16 operands (device globals: allocation-free rule)
__device__ __align__(128) __nv_bfloat16 g_xh[(size_t)M_*E_];
__device__ __align__(128) __nv_bfloat16 g_xl[(size_t)M_*E_];
__device__ __align__(128) __nv_bfloat16 g_wh[(size_t)4*E_*E_];
__device__ __align__(128) __nv_bfloat16 g_wl[(size_t)4*E_*E_];
__device__ __align__(128) __nv_bfloat16 g_qh[(size_t)B_*H_*S_*D_];
__device__ __align__(128) __nv_bfloat16 g_ql[(size_t)B_*H_*S_*D_];
__device__ __align__(128) __nv_bfloat16 g_kh[(size_t)B_*H_*S_*D_];
__device__ __align__(128) __nv_bfloat16 g_kl[(size_t)B_*H_*S_*D_];
__device__ __align__(128) __nv_bfloat16 g_vth[(size_t)B_*H_*D_*SP_];
__device__ __align__(128) __nv_bfloat16 g_vtl[(size_t)B_*H_*D_*SP_];
__device__ __align__(128) __nv_bfloat16 g_ch[(size_t)M_*E_];
__device__ __align__(128) __nv_bfloat16 g_cl[(size_t)M_*E_];

__device__ __forceinline__ uint32_t sptr(const void* p) {
    return (uint32_t)__cvta_generic_to_shared(p);
}
__device__ __forceinline__ void ldsm4(uint32_t* r, uint32_t a) {
    asm volatile("ldmatrix.sync.aligned.m8n8.x4.shared.b16 {%0,%1,%2,%3},[%4];"
                 : "=r"(r[0]), "=r"(r[1]), "=r"(r[2]), "=r"(r[3]) : "r"(a));
}
__device__ __forceinline__ void mma16816(float* c, const uint32_t* a,
                                         uint32_t b0, uint32_t b1) {
    asm volatile(
        "mma.sync.aligned.m16n8k16.row.col.f32.bf16.bf16.f32 "
        "{%0,%1,%2,%3},{%4,%5,%6,%7},{%8,%9},{%0,%1,%2,%3};"
        : "+f"(c[0]), "+f"(c[1]), "+f"(c[2]), "+f"(c[3])
        : "r"(a[0]), "r"(a[1]), "r"(a[2]), "r"(a[3]), "r"(b0), "r"(b1));
}
__device__ __forceinline__ void split_pack(float x, float y, uint32_t& hi, uint32_t& lo) {
    __nv_bfloat16 hx = __float2bfloat16_rn(x), hy = __float2bfloat16_rn(y);
    __nv_bfloat16 lx = __float2bfloat16_rn(x - __bfloat162float(hx));
    __nv_bfloat16 ly = __float2bfloat16_rn(y - __bfloat162float(hy));
    __nv_bfloat162 hh; hh.x = hx; hh.y = hy;
    __nv_bfloat162 ll; ll.x = lx; ll.y = ly;
    hi = *reinterpret_cast<uint32_t*>(&hh);
    lo = *reinterpret_cast<uint32_t*>(&ll);
}

// ---------------------------------------------------------------------------
// Prologue: split fp32 -> bf16 hi/lo.  sel 0: -> g_xh/g_xl; sel 1: -> g_w*+off
// ---------------------------------------------------------------------------
__global__ __launch_bounds__(256) void splitk(const float4* __restrict__ src,
                                              int sel, size_t off, int n4)
{
    int i = blockIdx.x * 256 + threadIdx.x;
    if (i >= n4) return;
    __nv_bfloat16 *h, *l;
    if (sel == 0) { h = g_xh; l = g_xl; } else { h = g_wh + off; l = g_wl + off; }
    float4 v = src[i];
    uint32_t h01, l01, h23, l23;
    split_pack(v.x, v.y, h01, l01);
    split_pack(v.z, v.w, h23, l23);
    *(uint2*)&h[(size_t)i*4] = make_uint2(h01, h23);
    *(uint2*)&l[(size_t)i*4] = make_uint2(l01, l23);
}

// ---------------------------------------------------------------------------
// Split-bf16 tensor GEMM (round-8 structure, pre-split operands, pass-major).
// 128x128x32 tiles, 256 thr (8 warps, 4x2), register-prefetch pipelining.
// mode 0: fp32 [M,E]+bias (A=ctx split).  1: ->q hi/lo (+b)*0.125.
// mode 2: ->k hi/lo.  3: ->v^T hi/lo [b,h,d,s] (+b).
// ---------------------------------------------------------------------------
__global__ __launch_bounds__(256) void gemm_v3(const float* __restrict__ bias,
                                               float* __restrict__ out, int mode)
{
    extern __shared__ __nv_bfloat16 dsm[];
    __nv_bfloat16* sA = dsm;             // [khalf(2)][hl(2)] x 128 x GS
    __nv_bfloat16* sB = dsm + 4*128*GS;

    const __nv_bfloat16 *Ah, *Al;
    if (mode == 0) { Ah = g_ch; Al = g_cl; } else { Ah = g_xh; Al = g_xl; }
    size_t woff = (size_t)((mode == 0) ? 3 : (mode - 1)) * E_ * E_;
    const __nv_bfloat16 *Bh = g_wh + woff, *Bl = g_wl + woff;

    int tid = threadIdx.x, lane = tid & 31, warp = tid >> 5;
    int m0 = blockIdx.x * 128, n0 = blockIdx.y * 128;
    int wm = (warp >> 1) * 32, wn = (warp & 1) * 64;

    float acc[2][8][4];
#pragma unroll
    for (int a = 0; a < 2; a++)
#pragma unroll
        for (int nb = 0; nb < 8; nb++)
#pragma unroll
            for (int r = 0; r < 4; r++) acc[a][nb][r] = 0.f;

    // loader: thread -> (row = tid>>1, k-half = tid&1); 16 elems per array
    int lrow = tid >> 1, lch = tid & 1;
    bool mok = (m0 + lrow) < M_;
    const __nv_bfloat16* aph = Ah + (size_t)(m0 + lrow) * E_ + lch * 16;
    const __nv_bfloat16* apl = Al + (size_t)(m0 + lrow) * E_ + lch * 16;
    const __nv_bfloat16* bph = Bh + (size_t)(n0 + lrow) * E_ + lch * 16;
    const __nv_bfloat16* bpl = Bl + (size_t)(n0 + lrow) * E_ + lch * 16;

    uint4 va[2], vla[2], vb[2], vlb[2];
    const uint4 Z = make_uint4(0u,0u,0u,0u);
#pragma unroll
    for (int i = 0; i < 2; i++) {
        va[i]  = mok ? *(const uint4*)(aph + i*8) : Z;
        vla[i] = mok ? *(const uint4*)(apl + i*8) : Z;
        vb[i]  = *(const uint4*)(bph + i*8);
        vlb[i] = *(const uint4*)(bpl + i*8);
    }

    int arow = wm + (lane & 7) + ((lane >> 3) & 1) * 8;
    int brow = wn + (lane & 7) + (lane >> 4) * 8;

    const int NK = E_ / 32;   // 40
    for (int kc = 0; kc < NK; kc++) {
        __syncthreads();
        {
            int bh_ = (lch*2+0)*128*GS + lrow*GS;
            int bl_ = (lch*2+1)*128*GS + lrow*GS;
            *(uint4*)&sA[bh_]     = va[0];  *(uint4*)&sA[bh_ + 8] = va[1];
            *(uint4*)&sA[bl_]     = vla[0]; *(uint4*)&sA[bl_ + 8] = vla[1];
            *(uint4*)&sB[bh_]     = vb[0];  *(uint4*)&sB[bh_ + 8] = vb[1];
            *(uint4*)&sB[bl_]     = vlb[0]; *(uint4*)&sB[bl_ + 8] = vlb[1];
        }
        __syncthreads();
        if (kc + 1 < NK) {
            size_t go = (size_t)(kc + 1) * 32;
#pragma unroll
            for (int i = 0; i < 2; i++) {
                va[i]  = mok ? *(const uint4*)(aph + go + i*8) : Z;
                vla[i] = mok ? *(const uint4*)(apl + go + i*8) : Z;
                vb[i]  = *(const uint4*)(bph + go + i*8);
                vlb[i] = *(const uint4*)(bpl + go + i*8);
            }
        }
#pragma unroll
        for (int cc = 0; cc < 2; cc++) {
            uint32_t ah[2][4], al[2][4];
            int akof = (lane >> 4) * 8;
#pragma unroll
            for (int a = 0; a < 2; a++) {
                ldsm4(ah[a], sptr(&sA[(cc*2+0)*128*GS + (arow+a*16)*GS + akof]));
                ldsm4(al[a], sptr(&sA[(cc*2+1)*128*GS + (arow+a*16)*GS + akof]));
            }
            int bkof = ((lane >> 3) & 1) * 8;
            uint32_t bh[4][4], bl[4][4];
#pragma unroll
            for (int p = 0; p < 4; p++) {
                ldsm4(bh[p], sptr(&sB[(cc*2+0)*128*GS + (brow+p*16)*GS + bkof]));
                ldsm4(bl[p], sptr(&sB[(cc*2+1)*128*GS + (brow+p*16)*GS + bkof]));
            }
            // pass-major: avoid back-to-back same-accumulator mma
#pragma unroll
            for (int pass = 0; pass < 3; pass++) {
#pragma unroll
                for (int a = 0; a < 2; a++) {
                    const uint32_t* af = (pass < 2) ? ah[a] : al[a];
#pragma unroll
                    for (int nb = 0; nb < 8; nb++) {
                        const uint32_t (*bf)[4] = (pass == 1) ? bl : bh;
                        mma16816(acc[a][nb], af,
                                 bf[nb>>1][(nb&1)*2], bf[nb>>1][(nb&1)*2+1]);
                    }
                }
            }
        }
    }

    // epilogue
#pragma unroll
    for (int a = 0; a < 2; a++)
#pragma unroll
        for (int rr = 0; rr < 2; rr++) {
            int gm = m0 + wm + a*16 + (lane >> 2) + rr*8;
            if (gm >= M_) continue;
            int bb = gm / S_, ss = gm % S_;
#pragma unroll
            for (int nb = 0; nb < 8; nb++) {
                int n = n0 + wn + nb*8 + (lane & 3)*2;
                float v0 = acc[a][nb][rr*2+0], v1 = acc[a][nb][rr*2+1];
                if (mode == 0) {
                    float2 o; o.x = v0 + bias[n]; o.y = v1 + bias[n+1];
                    *(float2*)&out[(size_t)gm*E_ + n] = o;
                } else {
                    if (mode == 1) { v0 = (v0+bias[n])*0.125f; v1 = (v1+bias[n+1])*0.125f; }
                    else if (mode == 3) { v0 += bias[n]; v1 += bias[n+1]; }
                    int hh = n >> 6, dd = n & 63;
                    uint32_t hi, lo;
                    split_pack(v0, v1, hi, lo);
                    if (mode == 3) {
                        size_t base = (((size_t)bb*H_ + hh)*D_ + dd)*SP_ + ss;
                        __nv_bfloat162 Hh = *(__nv_bfloat162*)&hi;
                        __nv_bfloat162 Ll = *(__nv_bfloat162*)&lo;
                        g_vth[base] = Hh.x; g_vth[base+SP_] = Hh.y;
                        g_vtl[base] = Ll.x; g_vtl[base+SP_] = Ll.y;
                    } else {
                        size_t idx = (((size_t)bb*H_ + hh)*S_ + ss)*D_ + dd;
                        if (mode == 1) { *(uint32_t*)&g_qh[idx] = hi; *(uint32_t*)&g_ql[idx] = lo; }
                        else           { *(uint32_t*)&g_kh[idx] = hi; *(uint32_t*)&g_kl[idx] = lo; }
                    }
                }
            }
        }
}

// ---------------------------------------------------------------------------
// Tensor-core flash attention (round-8 structure): 128 thr, 64 q rows/block,
// 64-key chunks, fragment softmax, in-register P repack, pass-major mma.
// Epilogue writes ctx as split bf16 (g_ch/g_cl).
// ---------------------------------------------------------------------------
__global__ __launch_bounds__(128) void attn_tc(const float* __restrict__ mask)
{
    __shared__ __align__(16) __nv_bfloat16 sK[2*64*AS];
    __shared__ __align__(16) __nv_bfloat16 sV[2*64*AS];

    int tid = threadIdx.x, lane = tid & 31, warp = tid >> 5;
    int qb = blockIdx.x, bh = blockIdx.y;
    int b = bh / H_;
    const __nv_bfloat16* qhp = g_qh  + (size_t)bh*S_*D_;
    const __nv_bfloat16* qlp = g_ql  + (size_t)bh*S_*D_;
    const __nv_bfloat16* khp = g_kh  + (size_t)bh*S_*D_;
    const __nv_bfloat16* klp = g_kl  + (size_t)bh*S_*D_;
    const __nv_bfloat16* vhp = g_vth + (size_t)bh*D_*SP_;
    const __nv_bfloat16* vlp = g_vtl + (size_t)bh*D_*SP_;
    int s0q = qb * 64;

    // stage Q (hi/lo) via sK, build persistent A fragments
#pragma unroll
    for (int it = 0; it < 8; it++) {
        int idx = it*128 + tid;
        int hl = idx >> 9, r = (idx >> 3) & 63, c8 = idx & 7;
        const __nv_bfloat16* src = hl ? qlp : qhp;
        uint4 v = make_uint4(0u,0u,0u,0u);
        if (s0q + r < S_) v = *(const uint4*)(src + (size_t)(s0q+r)*D_ + c8*8);
        *(uint4*)&sK[hl*64*AS + r*AS + c8*8] = v;
    }
    __syncthreads();

    uint32_t qf[2][4][4];
    {
        int arow = warp*16 + (lane & 7) + ((lane >> 3) & 1)*8;
        int akof = (lane >> 4)*8;
#pragma unroll
        for (int hl = 0; hl < 2; hl++)
#pragma unroll
            for (int kb = 0; kb < 4; kb++)
                ldsm4(qf[hl][kb], sptr(&sK[hl*64*AS + arow*AS + kb*16 + akof]));
    }
    __syncthreads();

    float oacc[8][4];
#pragma unroll
    for (int d = 0; d < 8; d++)
#pragma unroll
        for (int r = 0; r < 4; r++) oacc[d][r] = 0.f;
    float mi0 = -1e30f, mi1 = -1e30f, li0 = 0.f, li1 = 0.f;

    int r0 = warp*16 + (lane >> 2);
    int sq0 = s0q + r0, sq1 = sq0 + 8;
    const float* mrow0 = mask + ((size_t)b*S_ + (sq0 < S_ ? sq0 : S_-1))*S_;
    const float* mrow1 = mask + ((size_t)b*S_ + (sq1 < S_ ? sq1 : S_-1))*S_;

    int brow = (lane & 7) + (lane >> 4)*8;
    int bkof = ((lane >> 3) & 1)*8;

    const int NC = (S_ + 63) / 64;   // 24
    for (int kc = 0; kc < NC; kc++) {
        int s0 = kc * 64;
        if (s0 + 64 <= S_) {
#pragma unroll
            for (int it = 0; it < 8; it++) {
                int idx = it*128 + tid;
                int hl = idx >> 9, r = (idx >> 3) & 63, c8 = idx & 7;
                const __nv_bfloat16* ks = hl ? klp : khp;
                const __nv_bfloat16* vs = hl ? vlp : vhp;
                *(uint4*)&sK[hl*64*AS + r*AS + c8*8] =
                    *(const uint4*)(ks + (size_t)(s0+r)*D_ + c8*8);
                *(uint4*)&sV[hl*64*AS + r*AS + c8*8] =
                    *(const uint4*)(vs + (size_t)r*SP_ + s0 + c8*8);
            }
        } else {
#pragma unroll
            for (int it = 0; it < 8; it++) {
                int idx = it*128 + tid;
                int hl = idx >> 9, r = (idx >> 3) & 63, c8 = idx & 7;
                const __nv_bfloat16* ks = hl ? klp : khp;
                const __nv_bfloat16* vs = hl ? vlp : vhp;
                uint4 kv = make_uint4(0u,0u,0u,0u);
                if (s0 + r < S_) kv = *(const uint4*)(ks + (size_t)(s0+r)*D_ + c8*8);
                *(uint4*)&sK[hl*64*AS + r*AS + c8*8] = kv;
                uint4 vv; __nv_bfloat16* tp = (__nv_bfloat16*)&vv;
#pragma unroll
                for (int e = 0; e < 8; e++) {
                    int s = s0 + c8*8 + e;
                    tp[e] = (s < S_) ? vs[(size_t)r*SP_ + s] : __float2bfloat16_rn(0.f);
                }
                *(uint4*)&sV[hl*64*AS + r*AS + c8*8] = vv;
            }
        }
        __syncthreads();

        // S = Q @ K^T (3-pass split, pass-major)
        float sc[8][4];
#pragma unroll
        for (int nb = 0; nb < 8; nb++)
#pragma unroll
            for (int r = 0; r < 4; r++) sc[nb][r] = 0.f;
#pragma unroll
        for (int kb = 0; kb < 4; kb++) {
            uint32_t khf[4][4], klf[4][4];
#pragma unroll
            for (int p = 0; p < 4; p++) {
                ldsm4(khf[p], sptr(&sK[0*64*AS + (brow+p*16)*AS + kb*16 + bkof]));
                ldsm4(klf[p], sptr(&sK[1*64*AS + (brow+p*16)*AS + kb*16 + bkof]));
            }
#pragma unroll
            for (int pass = 0; pass < 3; pass++) {
                const uint32_t* af = (pass < 2) ? qf[0][kb] : qf[1][kb];
#pragma unroll
                for (int nb = 0; nb < 8; nb++) {
                    const uint32_t (*bf)[4] = (pass == 1) ? klf : khf;
                    mma16816(sc[nb], af, bf[nb>>1][(nb&1)*2], bf[nb>>1][(nb&1)*2+1]);
                }
            }
        }

        // mask + online softmax
        float mnew0 = mi0, mnew1 = mi1;
        int colb = s0 + (lane & 3)*2;
#pragma unroll
        for (int nb = 0; nb < 8; nb++) {
            int col = colb + nb*8;
            float2 mk0 = make_float2(-1e30f, -1e30f), mk1 = mk0;
            if (col < S_) { mk0 = *(const float2*)(mrow0 + col);
                            mk1 = *(const float2*)(mrow1 + col); }
            sc[nb][0] += mk0.x; sc[nb][1] += mk0.y;
            sc[nb][2] += mk1.x; sc[nb][3] += mk1.y;
            mnew0 = fmaxf(mnew0, fmaxf(sc[nb][0], sc[nb][1]));
            mnew1 = fmaxf(mnew1, fmaxf(sc[nb][2], sc[nb][3]));
        }
        mnew0 = fmaxf(mnew0, __shfl_xor_sync(0xffffffffu, mnew0, 1));
        mnew0 = fmaxf(mnew0, __shfl_xor_sync(0xffffffffu, mnew0, 2));
        mnew1 = fmaxf(mnew1, __shfl_xor_sync(0xffffffffu, mnew1, 1));
        mnew1 = fmaxf(mnew1, __shfl_xor_sync(0xffffffffu, mnew1, 2));
        float corr0 = __expf(mi0 - mnew0), corr1 = __expf(mi1 - mnew1);
        float rs0 = 0.f, rs1 = 0.f;
#pragma unroll
        for (int nb = 0; nb < 8; nb++) {
            sc[nb][0] = __expf(sc[nb][0] - mnew0);
            sc[nb][1] = __expf(sc[nb][1] - mnew0);
            sc[nb][2] = __expf(sc[nb][2] - mnew1);
            sc[nb][3] = __expf(sc[nb][3] - mnew1);
            rs0 += sc[nb][0] + sc[nb][1];
            rs1 += sc[nb][2] + sc[nb][3];
        }
        rs0 += __shfl_xor_sync(0xffffffffu, rs0, 1);
        rs0 += __shfl_xor_sync(0xffffffffu, rs0, 2);
        rs1 += __shfl_xor_sync(0xffffffffu, rs1, 1);
        rs1 += __shfl_xor_sync(0xffffffffu, rs1, 2);
        li0 = li0*corr0 + rs0; li1 = li1*corr1 + rs1;
        mi0 = mnew0; mi1 = mnew1;
#pragma unroll
        for (int d = 0; d < 8; d++) {
            oacc[d][0] *= corr0; oacc[d][1] *= corr0;
            oacc[d][2] *= corr1; oacc[d][3] *= corr1;
        }

        // O += P @ V (in-register P repack, 3-pass split, pass-major)
#pragma unroll
        for (int kb = 0; kb < 4; kb++) {
            uint32_t ph[4], pl[4];
            split_pack(sc[2*kb][0],   sc[2*kb][1],   ph[0], pl[0]);
            split_pack(sc[2*kb][2],   sc[2*kb][3],   ph[1], pl[1]);
            split_pack(sc[2*kb+1][0], sc[2*kb+1][1], ph[2], pl[2]);
            split_pack(sc[2*kb+1][2], sc[2*kb+1][3], ph[3], pl[3]);
            uint32_t vhf[4][4], vlf[4][4];
#pragma unroll
            for (int p = 0; p < 4; p++) {
                ldsm4(vhf[p], sptr(&sV[0*64*AS + (brow+p*16)*AS + kb*16 + bkof]));
                ldsm4(vlf[p], sptr(&sV[1*64*AS + (brow+p*16)*AS + kb*16 + bkof]));
            }
#pragma unroll
            for (int pass = 0; pass < 3; pass++) {
                const uint32_t* af = (pass < 2) ? ph : pl;
#pragma unroll
                for (int db = 0; db < 8; db++) {
                    const uint32_t (*bf)[4] = (pass == 1) ? vlf : vhf;
                    mma16816(oacc[db], af, bf[db>>1][(db&1)*2], bf[db>>1][(db&1)*2+1]);
                }
            }
        }
        __syncthreads();
    }

    float inv0 = 1.f/li0, inv1 = 1.f/li1;
    int hcol = (bh % H_) * 64;
#pragma unroll
    for (int db = 0; db < 8; db++) {
        int col = hcol + db*8 + (lane & 3)*2;
        if (sq0 < S_) {
            uint32_t hi, lo;
            split_pack(oacc[db][0]*inv0, oacc[db][1]*inv0, hi, lo);
            size_t idx = ((size_t)b*S_ + sq0)*E_ + col;
            *(uint32_t*)&g_ch[idx] = hi; *(uint32_t*)&g_cl[idx] = lo;
        }
        if (sq1 < S_) {
            uint32_t hi, lo;
            split_pack(oacc[db][2]*inv1, oacc[db][3]*inv1, hi, lo);
            size_t idx = ((size_t)b*S_ + sq1)*E_ + col;
            *(uint32_t*)&g_ch[idx] = hi; *(uint32_t*)&g_cl[idx] = lo;
        }
    }
}

// ---------------------------------------------------------------------------
extern "C" void kernel_launch(void* const* d_in, const int* in_sizes, int n_in,
                              void* d_out, int out_size)
{
    const float* x    = (const float*)d_in[0];
    const float* mask = (const float*)d_in[1];
    const float* Wq   = (const float*)d_in[2];
    const float* bq   = (const float*)d_in[3];
    const float* Wk   = (const float*)d_in[4];
    const float* Wv   = (const float*)d_in[5];
    const float* bv   = (const float*)d_in[6];
    const float* Wo   = (const float*)d_in[7];
    const float* bo   = (const float*)d_in[8];
    float* out = (float*)d_out;

    const int GSMEM = 8 * 128 * GS * (int)sizeof(__nv_bfloat16);  // 49152 B
    cudaFuncSetAttribute(gemm_v3, cudaFuncAttributeMaxDynamicSharedMemorySize, GSMEM);

    // prologue: split fp32 operands into persistent bf16 hi/lo
    int n4x = M_ * E_ / 4;
    int n4w = E_ * E_ / 4;
    splitk<<<(n4x + 255) / 256, 256>>>((const float4*)x,  0, 0, n4x);
    splitk<<<(n4w + 255) / 256, 256>>>((const float4*)Wq, 1, (size_t)0*E_*E_, n4w);
    splitk<<<(n4w + 255) / 256, 256>>>((const float4*)Wk, 1, (size_t)1*E_*E_, n4w);
    splitk<<<(n4w + 255) / 256, 256>>>((const float4*)Wv, 1, (size_t)2*E_*E_, n4w);
    splitk<<<(n4w + 255) / 256, 256>>>((const float4*)Wo, 1, (size_t)3*E_*E_, n4w);

    dim3 ggrid((M_ + 127) / 128, E_ / 128);          // (47, 10)
    gemm_v3<<<ggrid, 256, GSMEM>>>(bq, nullptr, 1);
    gemm_v3<<<ggrid, 256, GSMEM>>>(nullptr, nullptr, 2);
    gemm_v3<<<ggrid, 256, GSMEM>>>(bv, nullptr, 3);

    dim3 agrid((S_ + 63) / 64, B_ * H_);             // (24, 80)
    attn_tc<<<agrid, 128>>>(mask);

    gemm_v3<<<ggrid, 256, GSMEM>>>(bo, out, 0);
}

// round 12
// speedup vs baseline: 1.2396x; 1.0848x over previous
#include <cuda_runtime.h>
#include <cuda_bf16.h>
#include <stdint.h>
#include <math.h>

#define B_ 4
#define S_ 1500
#define SP_ 1504
#define E_ 1280
#define H_ 20
#define D_ 64
#define M_ 6000
#define GS 24           // gemm smem row stride (elems)
#define AS 72           // attn smem row stride

// Persistent split-bf16 operands (device globals: allocation-free rule)
__device__ __align__(128) __nv_bfloat16 g_xh[(size_t)M_*E_];
__device__ __align__(128) __nv_bfloat16 g_xl[(size_t)M_*E_];
__device__ __align__(128) __nv_bfloat16 g_wh[(size_t)4*E_*E_];
__device__ __align__(128) __nv_bfloat16 g_wl[(size_t)4*E_*E_];
__device__ __align__(128) __nv_bfloat16 g_qh[(size_t)B_*H_*S_*D_];
__device__ __align__(128) __nv_bfloat16 g_ql[(size_t)B_*H_*S_*D_];
__device__ __align__(128) __nv_bfloat16 g_kh[(size_t)B_*H_*S_*D_];
__device__ __align__(128) __nv_bfloat16 g_kl[(size_t)B_*H_*S_*D_];
__device__ __align__(128) __nv_bfloat16 g_vth[(size_t)B_*H_*D_*SP_];
__device__ __align__(128) __nv_bfloat16 g_vtl[(size_t)B_*H_*D_*SP_];
__device__ __align__(128) __nv_bfloat16 g_ch[(size_t)M_*E_];
__device__ __align__(128) __nv_bfloat16 g_cl[(size_t)M_*E_];

__device__ __forceinline__ uint32_t sptr(const void* p) {
    return (uint32_t)__cvta_generic_to_shared(p);
}
__device__ __forceinline__ void ldsm4(uint32_t* r, uint32_t a) {
    asm volatile("ldmatrix.sync.aligned.m8n8.x4.shared.b16 {%0,%1,%2,%3},[%4];"
                 : "=r"(r[0]), "=r"(r[1]), "=r"(r[2]), "=r"(r[3]) : "r"(a));
}
__device__ __forceinline__ void mma16816(float* c, const uint32_t* a,
                                         uint32_t b0, uint32_t b1) {
    asm volatile(
        "mma.sync.aligned.m16n8k16.row.col.f32.bf16.bf16.f32 "
        "{%0,%1,%2,%3},{%4,%5,%6,%7},{%8,%9},{%0,%1,%2,%3};"
        : "+f"(c[0]), "+f"(c[1]), "+f"(c[2]), "+f"(c[3])
        : "r"(a[0]), "r"(a[1]), "r"(a[2]), "r"(a[3]), "r"(b0), "r"(b1));
}
__device__ __forceinline__ void split_pack(float x, float y, uint32_t& hi, uint32_t& lo) {
    __nv_bfloat16 hx = __float2bfloat16_rn(x), hy = __float2bfloat16_rn(y);
    __nv_bfloat16 lx = __float2bfloat16_rn(x - __bfloat162float(hx));
    __nv_bfloat16 ly = __float2bfloat16_rn(y - __bfloat162float(hy));
    __nv_bfloat162 hh; hh.x = hx; hh.y = hy;
    __nv_bfloat162 ll; ll.x = lx; ll.y = ly;
    hi = *reinterpret_cast<uint32_t*>(&hh);
    lo = *reinterpret_cast<uint32_t*>(&ll);
}
// cp.async 16B with zero-fill when !ok (src must still be a valid address)
__device__ __forceinline__ void cpa16z(uint32_t dst, const void* src, int ok) {
    asm volatile(
        "{\n\t.reg .pred p;\n\t.reg .b32 sz;\n\t"
        "setp.ne.b32 p, %2, 0;\n\t"
        "selp.b32 sz, 16, 0, p;\n\t"
        "cp.async.ca.shared.global [%0], [%1], 16, sz;\n\t}"
        :: "r"(dst), "l"(src), "r"(ok));
}

// ---------------------------------------------------------------------------
// Prologue: split fp32 -> bf16 hi/lo.
// ---------------------------------------------------------------------------
__global__ __launch_bounds__(256) void splitk(const float4* __restrict__ src,
                                              int sel, size_t off, int n4)
{
    int i = blockIdx.x * 256 + threadIdx.x;
    if (i >= n4) return;
    __nv_bfloat16 *h, *l;
    if (sel == 0) { h = g_xh; l = g_xl; } else { h = g_wh + off; l = g_wl + off; }
    float4 v = src[i];
    uint32_t h01, l01, h23, l23;
    split_pack(v.x, v.y, h01, l01);
    split_pack(v.z, v.w, h23, l23);
    *(uint2*)&h[(size_t)i*4] = make_uint2(h01, h23);
    *(uint2*)&l[(size_t)i*4] = make_uint2(l01, l23);
}

// ---------------------------------------------------------------------------
// Split-bf16 mma.sync GEMM (round-10 proven tile, merged-QKV grid mapping).
// modeArg < 0: merged QKV — blockIdx.y/10 selects {q,k,v}; b1=bq, b2=bv.
// modeArg == 0: final projection — A=ctx split, W=Wo, bias=b2=bo, out fp32.
// ---------------------------------------------------------------------------
__global__ __launch_bounds__(256) void gemm_v3(const float* __restrict__ b1,
                                               const float* __restrict__ b2,
                                               float* __restrict__ out,
                                               int modeArg)
{
    extern __shared__ __nv_bfloat16 dsm[];
    __nv_bfloat16* sA = dsm;             // [khalf(2)][hl(2)] x 128 x GS
    __nv_bfloat16* sB = dsm + 4*128*GS;

    int mode, wsel, n0;
    if (modeArg < 0) { wsel = blockIdx.y / 10; n0 = (blockIdx.y % 10) * 128; mode = wsel + 1; }
    else             { wsel = 3; n0 = blockIdx.y * 128; mode = 0; }
    const float* bias = (mode == 1) ? b1 : b2;   // mode 2 never reads bias

    const __nv_bfloat16 *Ah, *Al;
    if (mode == 0) { Ah = g_ch; Al = g_cl; } else { Ah = g_xh; Al = g_xl; }
    const __nv_bfloat16 *Bh = g_wh + (size_t)wsel * E_ * E_;
    const __nv_bfloat16 *Bl = g_wl + (size_t)wsel * E_ * E_;

    int tid = threadIdx.x, lane = tid & 31, warp = tid >> 5;
    int m0 = blockIdx.x * 128;
    int wm = (warp >> 1) * 32, wn = (warp & 1) * 64;

    float acc[2][8][4];
#pragma unroll
    for (int a = 0; a < 2; a++)
#pragma unroll
        for (int nb = 0; nb < 8; nb++)
#pragma unroll
            for (int r = 0; r < 4; r++) acc[a][nb][r] = 0.f;

    int lrow = tid >> 1, lch = tid & 1;
    bool mok = (m0 + lrow) < M_;
    const __nv_bfloat16* aph = Ah + (size_t)(m0 + lrow) * E_ + lch * 16;
    const __nv_bfloat16* apl = Al + (size_t)(m0 + lrow) * E_ + lch * 16;
    const __nv_bfloat16* bph = Bh + (size_t)(n0 + lrow) * E_ + lch * 16;
    const __nv_bfloat16* bpl = Bl + (size_t)(n0 + lrow) * E_ + lch * 16;

    uint4 va[2], vla[2], vb[2], vlb[2];
    const uint4 Z = make_uint4(0u,0u,0u,0u);
#pragma unroll
    for (int i = 0; i < 2; i++) {
        va[i]  = mok ? *(const uint4*)(aph + i*8) : Z;
        vla[i] = mok ? *(const uint4*)(apl + i*8) : Z;
        vb[i]  = *(const uint4*)(bph + i*8);
        vlb[i] = *(const uint4*)(bpl + i*8);
    }

    int arow = wm + (lane & 7) + ((lane >> 3) & 1) * 8;
    int brow = wn + (lane & 7) + (lane >> 4) * 8;

    const int NK = E_ / 32;   // 40
    for (int kc = 0; kc < NK; kc++) {
        __syncthreads();
        {
            int bh_ = (lch*2+0)*128*GS + lrow*GS;
            int bl_ = (lch*2+1)*128*GS + lrow*GS;
            *(uint4*)&sA[bh_]     = va[0];  *(uint4*)&sA[bh_ + 8] = va[1];
            *(uint4*)&sA[bl_]     = vla[0]; *(uint4*)&sA[bl_ + 8] = vla[1];
            *(uint4*)&sB[bh_]     = vb[0];  *(uint4*)&sB[bh_ + 8] = vb[1];
            *(uint4*)&sB[bl_]     = vlb[0]; *(uint4*)&sB[bl_ + 8] = vlb[1];
        }
        __syncthreads();
        if (kc + 1 < NK) {
            size_t go = (size_t)(kc + 1) * 32;
#pragma unroll
            for (int i = 0; i < 2; i++) {
                va[i]  = mok ? *(const uint4*)(aph + go + i*8) : Z;
                vla[i] = mok ? *(const uint4*)(apl + go + i*8) : Z;
                vb[i]  = *(const uint4*)(bph + go + i*8);
                vlb[i] = *(const uint4*)(bpl + go + i*8);
            }
        }
#pragma unroll
        for (int cc = 0; cc < 2; cc++) {
            uint32_t ah[2][4], al[2][4];
            int akof = (lane >> 4) * 8;
#pragma unroll
            for (int a = 0; a < 2; a++) {
                ldsm4(ah[a], sptr(&sA[(cc*2+0)*128*GS + (arow+a*16)*GS + akof]));
                ldsm4(al[a], sptr(&sA[(cc*2+1)*128*GS + (arow+a*16)*GS + akof]));
            }
            int bkof = ((lane >> 3) & 1) * 8;
            uint32_t bh[4][4], bl[4][4];
#pragma unroll
            for (int p = 0; p < 4; p++) {
                ldsm4(bh[p], sptr(&sB[(cc*2+0)*128*GS + (brow+p*16)*GS + bkof]));
                ldsm4(bl[p], sptr(&sB[(cc*2+1)*128*GS + (brow+p*16)*GS + bkof]));
            }
#pragma unroll
            for (int pass = 0; pass < 3; pass++) {
#pragma unroll
                for (int a = 0; a < 2; a++) {
                    const uint32_t* af = (pass < 2) ? ah[a] : al[a];
#pragma unroll
                    for (int nb = 0; nb < 8; nb++) {
                        const uint32_t (*bf)[4] = (pass == 1) ? bl : bh;
                        mma16816(acc[a][nb], af,
                                 bf[nb>>1][(nb&1)*2], bf[nb>>1][(nb&1)*2+1]);
                    }
                }
            }
        }
    }

    // epilogue
#pragma unroll
    for (int a = 0; a < 2; a++)
#pragma unroll
        for (int rr = 0; rr < 2; rr++) {
            int gm = m0 + wm + a*16 + (lane >> 2) + rr*8;
            if (gm >= M_) continue;
            int bb = gm / S_, ss = gm % S_;
#pragma unroll
            for (int nb = 0; nb < 8; nb++) {
                int n = n0 + wn + nb*8 + (lane & 3)*2;
                float v0 = acc[a][nb][rr*2+0], v1 = acc[a][nb][rr*2+1];
                if (mode == 0) {
                    float2 o; o.x = v0 + bias[n]; o.y = v1 + bias[n+1];
                    *(float2*)&out[(size_t)gm*E_ + n] = o;
                } else {
                    if (mode == 1) { v0 = (v0+bias[n])*0.125f; v1 = (v1+bias[n+1])*0.125f; }
                    else if (mode == 3) { v0 += bias[n]; v1 += bias[n+1]; }
                    int hh = n >> 6, dd = n & 63;
                    uint32_t hi, lo;
                    split_pack(v0, v1, hi, lo);
                    if (mode == 3) {
                        size_t base = (((size_t)bb*H_ + hh)*D_ + dd)*SP_ + ss;
                        __nv_bfloat162 Hh = *(__nv_bfloat162*)&hi;
                        __nv_bfloat162 Ll = *(__nv_bfloat162*)&lo;
                        g_vth[base] = Hh.x; g_vth[base+SP_] = Hh.y;
                        g_vtl[base] = Ll.x; g_vtl[base+SP_] = Ll.y;
                    } else {
                        size_t idx = (((size_t)bb*H_ + hh)*S_ + ss)*D_ + dd;
                        if (mode == 1) { *(uint32_t*)&g_qh[idx] = hi; *(uint32_t*)&g_ql[idx] = lo; }
                        else           { *(uint32_t*)&g_kh[idx] = hi; *(uint32_t*)&g_kl[idx] = lo; }
                    }
                }
            }
        }
}

// ---------------------------------------------------------------------------
// Tensor-core flash attention with 2-stage cp.async K/V pipeline.
// 128 thr, 64 q rows/block; compute section identical to round-10.
// Dynamic smem: 2 stages x (K 2x64xAS + V 2x64xAS) bf16 = 73728 B.
// ---------------------------------------------------------------------------
#define ATILE (2*64*AS)          // elems per K (or V) tile, both hl halves
#define ASTG  (2*ATILE)          // elems per stage
#define ASMEM (2*ASTG*2)         // bytes total (x2 stages x2 B/elem)

__global__ __launch_bounds__(128) void attn_tc(const float* __restrict__ mask)
{
    extern __shared__ __align__(16) __nv_bfloat16 dsm[];

    int tid = threadIdx.x, lane = tid & 31, warp = tid >> 5;
    int qb = blockIdx.x, bh = blockIdx.y;
    int b = bh / H_;
    const __nv_bfloat16* qhp = g_qh  + (size_t)bh*S_*D_;
    const __nv_bfloat16* qlp = g_ql  + (size_t)bh*S_*D_;
    const __nv_bfloat16* khp = g_kh  + (size_t)bh*S_*D_;
    const __nv_bfloat16* klp = g_kl  + (size_t)bh*S_*D_;
    const __nv_bfloat16* vhp = g_vth + (size_t)bh*D_*SP_;
    const __nv_bfloat16* vlp = g_vtl + (size_t)bh*D_*SP_;
    int s0q = qb * 64;

    // stage Q (hi/lo) via stage-0 region, build persistent A fragments
#pragma unroll
    for (int it = 0; it < 8; it++) {
        int idx = it*128 + tid;
        int hl = idx >> 9, r = (idx >> 3) & 63, c8 = idx & 7;
        const __nv_bfloat16* src = hl ? qlp : qhp;
        uint4 v = make_uint4(0u,0u,0u,0u);
        if (s0q + r < S_) v = *(const uint4*)(src + (size_t)(s0q+r)*D_ + c8*8);
        *(uint4*)&dsm[hl*64*AS + r*AS + c8*8] = v;
    }
    __syncthreads();

    uint32_t qf[2][4][4];
    {
        int arow = warp*16 + (lane & 7) + ((lane >> 3) & 1)*8;
        int akof = (lane >> 4)*8;
#pragma unroll
        for (int hl = 0; hl < 2; hl++)
#pragma unroll
            for (int kb = 0; kb < 4; kb++)
                ldsm4(qf[hl][kb], sptr(&dsm[hl*64*AS + arow*AS + kb*16 + akof]));
    }
    __syncthreads();

    uint32_t sbase = sptr(dsm);
    const int NC = (S_ + 63) / 64;   // 24

    auto load_kv = [&](int kc, int s) {
        int s0 = kc * 64;
        uint32_t base = sbase + (uint32_t)s * (ASTG * 2);
#pragma unroll
        for (int it = 0; it < 16; it++) {
            int idx = it*128 + tid;            // 0..2047
            int isV = idx >> 10;
            int rem = idx & 1023;
            int hl = rem >> 9, r = (rem >> 3) & 63, c8 = rem & 7;
            uint32_t dst = base + (uint32_t)(isV * ATILE + hl*64*AS + r*AS + c8*8) * 2;
            if (!isV) {
                const __nv_bfloat16* ks = hl ? klp : khp;
                int ok = (s0 + r) < S_;
                const __nv_bfloat16* src = ks + (size_t)(ok ? (s0 + r) : 0) * D_ + c8*8;
                cpa16z(dst, src, ok);
            } else {
                const __nv_bfloat16* vs = hl ? vlp : vhp;
                int col = s0 + c8*8;
                int ok = (col + 8) <= SP_;
                const __nv_bfloat16* src = vs + (size_t)r * SP_ + (ok ? col : 0);
                cpa16z(dst, src, ok);
            }
        }
        asm volatile("cp.async.commit_group;");
    };

    load_kv(0, 0);
    load_kv(1, 1);

    float oacc[8][4];
#pragma unroll
    for (int d = 0; d < 8; d++)
#pragma unroll
        for (int r = 0; r < 4; r++) oacc[d][r] = 0.f;
    float mi0 = -1e30f, mi1 = -1e30f, li0 = 0.f, li1 = 0.f;

    int r0 = warp*16 + (lane >> 2);
    int sq0 = s0q + r0, sq1 = sq0 + 8;
    const float* mrow0 = mask + ((size_t)b*S_ + (sq0 < S_ ? sq0 : S_-1))*S_;
    const float* mrow1 = mask + ((size_t)b*S_ + (sq1 < S_ ? sq1 : S_-1))*S_;

    int brow = (lane & 7) + (lane >> 4)*8;
    int bkof = ((lane >> 3) & 1)*8;

    for (int kc = 0; kc < NC; kc++) {
        if (kc + 1 < NC) asm volatile("cp.async.wait_group 1;");
        else             asm volatile("cp.async.wait_group 0;");
        __syncthreads();

        const __nv_bfloat16* sK = dsm + (kc & 1) * ASTG;
        const __nv_bfloat16* sV = sK + ATILE;
        int s0 = kc * 64;

        // S = Q @ K^T (3-pass split, pass-major)
        float sc[8][4];
#pragma unroll
        for (int nb = 0; nb < 8; nb++)
#pragma unroll
            for (int r = 0; r < 4; r++) sc[nb][r] = 0.f;
#pragma unroll
        for (int kb = 0; kb < 4; kb++) {
            uint32_t khf[4][4], klf[4][4];
#pragma unroll
            for (int p = 0; p < 4; p++) {
                ldsm4(khf[p], sptr(&sK[0*64*AS + (brow+p*16)*AS + kb*16 + bkof]));
                ldsm4(klf[p], sptr(&sK[1*64*AS + (brow+p*16)*AS + kb*16 + bkof]));
            }
#pragma unroll
            for (int pass = 0; pass < 3; pass++) {
                const uint32_t* af = (pass < 2) ? qf[0][kb] : qf[1][kb];
#pragma unroll
                for (int nb = 0; nb < 8; nb++) {
                    const uint32_t (*bf)[4] = (pass == 1) ? klf : khf;
                    mma16816(sc[nb], af, bf[nb>>1][(nb&1)*2], bf[nb>>1][(nb&1)*2+1]);
                }
            }
        }

        // mask + online softmax
        float mnew0 = mi0, mnew1 = mi1;
        int colb = s0 + (lane & 3)*2;
#pragma unroll
        for (int nb = 0; nb < 8; nb++) {
            int col = colb + nb*8;
            float2 mk0 = make_float2(-1e30f, -1e30f), mk1 = mk0;
            if (col < S_) { mk0 = *(const float2*)(mrow0 + col);
                            mk1 = *(const float2*)(mrow1 + col); }
            sc[nb][0] += mk0.x; sc[nb][1] += mk0.y;
            sc[nb][2] += mk1.x; sc[nb][3] += mk1.y;
            mnew0 = fmaxf(mnew0, fmaxf(sc[nb][0], sc[nb][1]));
            mnew1 = fmaxf(mnew1, fmaxf(sc[nb][2], sc[nb][3]));
        }
        mnew0 = fmaxf(mnew0, __shfl_xor_sync(0xffffffffu, mnew0, 1));
        mnew0 = fmaxf(mnew0, __shfl_xor_sync(0xffffffffu, mnew0, 2));
        mnew1 = fmaxf(mnew1, __shfl_xor_sync(0xffffffffu, mnew1, 1));
        mnew1 = fmaxf(mnew1, __shfl_xor_sync(0xffffffffu, mnew1, 2));
        float corr0 = __expf(mi0 - mnew0), corr1 = __expf(mi1 - mnew1);
        float rs0 = 0.f, rs1 = 0.f;
#pragma unroll
        for (int nb = 0; nb < 8; nb++) {
            sc[nb][0] = __expf(sc[nb][0] - mnew0);
            sc[nb][1] = __expf(sc[nb][1] - mnew0);
            sc[nb][2] = __expf(sc[nb][2] - mnew1);
            sc[nb][3] = __expf(sc[nb][3] - mnew1);
            rs0 += sc[nb][0] + sc[nb][1];
            rs1 += sc[nb][2] + sc[nb][3];
        }
        rs0 += __shfl_xor_sync(0xffffffffu, rs0, 1);
        rs0 += __shfl_xor_sync(0xffffffffu, rs0, 2);
        rs1 += __shfl_xor_sync(0xffffffffu, rs1, 1);
        rs1 += __shfl_xor_sync(0xffffffffu, rs1, 2);
        li0 = li0*corr0 + rs0; li1 = li1*corr1 + rs1;
        mi0 = mnew0; mi1 = mnew1;
#pragma unroll
        for (int d = 0; d < 8; d++) {
            oacc[d][0] *= corr0; oacc[d][1] *= corr0;
            oacc[d][2] *= corr1; oacc[d][3] *= corr1;
        }

        // O += P @ V (in-register P repack, 3-pass split, pass-major)
#pragma unroll
        for (int kb = 0; kb < 4; kb++) {
            uint32_t ph[4], pl[4];
            split_pack(sc[2*kb][0],   sc[2*kb][1],   ph[0], pl[0]);
            split_pack(sc[2*kb][2],   sc[2*kb][3],   ph[1], pl[1]);
            split_pack(sc[2*kb+1][0], sc[2*kb+1][1], ph[2], pl[2]);
            split_pack(sc[2*kb+1][2], sc[2*kb+1][3], ph[3], pl[3]);
            uint32_t vhf[4][4], vlf[4][4];
#pragma unroll
            for (int p = 0; p < 4; p++) {
                ldsm4(vhf[p], sptr(&sV[0*64*AS + (brow+p*16)*AS + kb*16 + bkof]));
                ldsm4(vlf[p], sptr(&sV[1*64*AS + (brow+p*16)*AS + kb*16 + bkof]));
            }
#pragma unroll
            for (int pass = 0; pass < 3; pass++) {
                const uint32_t* af = (pass < 2) ? ph : pl;
#pragma unroll
                for (int db = 0; db < 8; db++) {
                    const uint32_t (*bf)[4] = (pass == 1) ? vlf : vhf;
                    mma16816(oacc[db], af, bf[db>>1][(db&1)*2], bf[db>>1][(db&1)*2+1]);
                }
            }
        }
        __syncthreads();
        if (kc + 2 < NC) load_kv(kc + 2, kc & 1);
    }

    float inv0 = 1.f/li0, inv1 = 1.f/li1;
    int hcol = (bh % H_) * 64;
#pragma unroll
    for (int db = 0; db < 8; db++) {
        int col = hcol + db*8 + (lane & 3)*2;
        if (sq0 < S_) {
            uint32_t hi, lo;
            split_pack(oacc[db][0]*inv0, oacc[db][1]*inv0, hi, lo);
            size_t idx = ((size_t)b*S_ + sq0)*E_ + col;
            *(uint32_t*)&g_ch[idx] = hi; *(uint32_t*)&g_cl[idx] = lo;
        }
        if (sq1 < S_) {
            uint32_t hi, lo;
            split_pack(oacc[db][2]*inv1, oacc[db][3]*inv1, hi, lo);
            size_t idx = ((size_t)b*S_ + sq1)*E_ + col;
            *(uint32_t*)&g_ch[idx] = hi; *(uint32_t*)&g_cl[idx] = lo;
        }
    }
}

// ---------------------------------------------------------------------------
extern "C" void kernel_launch(void* const* d_in, const int* in_sizes, int n_in,
                              void* d_out, int out_size)
{
    const float* x    = (const float*)d_in[0];
    const float* mask = (const float*)d_in[1];
    const float* Wq   = (const float*)d_in[2];
    const float* bq   = (const float*)d_in[3];
    const float* Wk   = (const float*)d_in[4];
    const float* Wv   = (const float*)d_in[5];
    const float* bv   = (const float*)d_in[6];
    const float* Wo   = (const float*)d_in[7];
    const float* bo   = (const float*)d_in[8];
    float* out = (float*)d_out;

    const int GSMEM = 8 * 128 * GS * (int)sizeof(__nv_bfloat16);  // 49152 B
    cudaFuncSetAttribute(gemm_v3, cudaFuncAttributeMaxDynamicSharedMemorySize, GSMEM);
    cudaFuncSetAttribute(attn_tc, cudaFuncAttributeMaxDynamicSharedMemorySize, ASMEM);

    // prologue: split fp32 operands into persistent bf16 hi/lo
    int n4x = M_ * E_ / 4;
    int n4w = E_ * E_ / 4;
    splitk<<<(n4x + 255) / 256, 256>>>((const float4*)x,  0, 0, n4x);
    splitk<<<(n4w + 255) / 256, 256>>>((const float4*)Wq, 1, (size_t)0*E_*E_, n4w);
    splitk<<<(n4w + 255) / 256, 256>>>((const float4*)Wk, 1, (size_t)1*E_*E_, n4w);
    splitk<<<(n4w + 255) / 256, 256>>>((const float4*)Wv, 1, (size_t)2*E_*E_, n4w);
    splitk<<<(n4w + 255) / 256, 256>>>((const float4*)Wo, 1, (size_t)3*E_*E_, n4w);

    // merged QKV projection: grid (47, 30)
    dim3 qkvgrid((M_ + 127) / 128, 3 * (E_ / 128));
    gemm_v3<<<qkvgrid, 256, GSMEM>>>(bq, bv, nullptr, -1);

    dim3 agrid((S_ + 63) / 64, B_ * H_);             // (24, 80)
    attn_tc<<<agrid, 128, ASMEM>>>(mask);

    dim3 ogrid((M_ + 127) / 128, E_ / 128);          // (47, 10)
    gemm_v3<<<ogrid, 256, GSMEM>>>(nullptr, bo, out, 0);
}